// round 17
// baseline (speedup 1.0000x reference)
#include <cuda_runtime.h>
#include <cuda_fp16.h>
#include <cstdint>
#include <math.h>

// Shapes (fixed)
#define QL 1024
#define CL 2048
#define BATCH 16
#define DIM 1024

// GEMM tiling: 128x64 block tile, BK=32 (two k16 substeps), 256 threads
#define BM 128
#define BN 64
#define NSTG 3

// smem sizes per instantiation (host-side mirror of in-kernel constants)
#define SMEM_22 (NSTG * (2 * 128 * 20 + 2 * 64 * 20) * 4)   // 92160 B
#define SMEM_11 (NSTG * (2 * 128 * 12 + 2 * 64 * 12) * 4)   // 55296 B

// Fused stage-1 grid: y in [0,8) = GEMM m-tiles, y in [8, 8+128) = c-split tiles
#define FUSE_YT 128     // 128 y-slots x 16 x-slots = 2048 transpose tiles/batch

// ---------------------------------------------------------------------------
// Split-plane scratch (fp16 hi/lo; lo pre-scaled by 2048)
// ---------------------------------------------------------------------------
__device__ __half g_qsph [(size_t)BATCH * QL * DIM];
__device__ __half g_qspl [(size_t)BATCH * QL * DIM];
__device__ __half g_csph [(size_t)BATCH * CL * DIM];
__device__ __half g_cspl [(size_t)BATCH * CL * DIM];
__device__ __half g_ctsph[(size_t)BATCH * DIM * CL];   // ct hi (stage 4 B)
__device__ __half g_wisph[(size_t)DIM * DIM];
__device__ __half g_wispl[(size_t)DIM * DIM];
__device__ __half g_wosph[(size_t)DIM * 2 * DIM];      // W_out hi (stage 5 B)
__device__ __half g_qbsph[(size_t)BATCH * QL * DIM];
__device__ __half g_qbspl[(size_t)BATCH * QL * DIM];
__device__ __half g_ssph [(size_t)BATCH * QL * CL];    // P hi (stage 4 A)
__device__ __half g_ctxsph[(size_t)BATCH * QL * DIM];  // ctx hi (stage 5 A)

// ---------------------------------------------------------------------------
// helpers
// ---------------------------------------------------------------------------
__device__ __forceinline__ void cp16(uint32_t dst, const void* src) {
    asm volatile("cp.async.cg.shared.global [%0], [%1], 16;" :: "r"(dst), "l"(src));
}
__device__ __forceinline__ void cp_commit() { asm volatile("cp.async.commit_group;" ::: "memory"); }
__device__ __forceinline__ void cp_wait1()  { asm volatile("cp.async.wait_group 1;"  ::: "memory"); }

__device__ __forceinline__ void mma16(float* d, const uint32_t* a, const uint32_t* b) {
    asm volatile(
        "mma.sync.aligned.m16n8k16.row.col.f32.f16.f16.f32 "
        "{%0,%1,%2,%3}, {%4,%5,%6,%7}, {%8,%9}, {%0,%1,%2,%3};"
        : "+f"(d[0]), "+f"(d[1]), "+f"(d[2]), "+f"(d[3])
        : "r"(a[0]), "r"(a[1]), "r"(a[2]), "r"(a[3]), "r"(b[0]), "r"(b[1]));
}

__device__ __forceinline__ void ldmx4(uint32_t* r, uint32_t a) {
    asm volatile("ldmatrix.sync.aligned.m8n8.x4.shared.b16 {%0,%1,%2,%3}, [%4];"
        : "=r"(r[0]), "=r"(r[1]), "=r"(r[2]), "=r"(r[3]) : "r"(a));
}
__device__ __forceinline__ void ldmx2(uint32_t* r, uint32_t a) {
    asm volatile("ldmatrix.sync.aligned.m8n8.x2.shared.b16 {%0,%1}, [%2];"
        : "=r"(r[0]), "=r"(r[1]) : "r"(a));
}

// fp16 split: hi = rn_fp16(f); lo = rn_fp16((f - hi) * 2048)   (lo pre-scaled)
__device__ __forceinline__ void splith(float f, __half& h, __half& l) {
    h = __float2half_rn(f);
    l = __float2half_rn((f - __half2float(h)) * 2048.0f);
}

// fast tanh: 1 - 2/(1 + e^{2x}); saturates correctly.
__device__ __forceinline__ float fast_tanh(float x) {
    return 1.0f - 2.0f / (1.0f + __expf(2.0f * x));
}

// ---------------------------------------------------------------------------
// C[m][n] = sum_k A[m][k]*B[n][k], fp32 result via fp16 planes.
//   AT/BT in {1,2}: planes per operand.  D = Ah*Bh (+Al*Bh) (+Ah*Bl);
//   lo planes pre-scaled by 2048, recombined as accH + accL/2048.
// MODE 0: split planes out (Cv=hi, Cv2=lo) | 1: fp32 | 2: tanh fp32 | 3: hi fp16
// FUSEC: CTAs with blockIdx.y >= 8 instead run a 32x32 c-split/transpose tile
//   (c[CL,B,DIM] -> csh/csl [B,CL,DIM] + cth [B,DIM,CL]), reusing dynamic smem.
//   These CTAs co-reside with the tensor-bound GEMM CTAs and hide the c
//   pre-pass's DRAM time under stage-1 compute.
// Smem row strides PA/PB = 20 b32 (2-plane) or 12 b32 (1-plane); both give
// conflict-free 8-phase ldmatrix banks. 1-plane variant: 55.3KB, 3 CTAs/SM.
// ---------------------------------------------------------------------------
template<int AT, int BT, int MODE, bool CONCAT, bool FUSEC>
__global__ __launch_bounds__(256, (AT == 1 && BT == 1) ? 3 : 2)
void gemm_h3_kernel(const __half* __restrict__ Ah, const __half* __restrict__ Al,
                    const __half* __restrict__ A1h, const __half* __restrict__ A1l,
                    long Abs, long lda,
                    const __half* __restrict__ Bh, const __half* __restrict__ Bl,
                    long Bbs, long ldb,
                    void* __restrict__ Cv, void* __restrict__ Cv2,
                    long Cbs, long ldc,
                    int K, int Ksplit,
                    const float* __restrict__ cfp,
                    __half* __restrict__ csh, __half* __restrict__ csl,
                    __half* __restrict__ cth)
{
    constexpr int PA = (AT == 2) ? 20 : 12;     // A row stride (b32)
    constexpr int PB = (BT == 2) ? 20 : 12;     // B row stride (b32)
    constexpr int A_SUBT = 128 * PA;            // b32 per k16 A subtile
    constexpr int B_SUBT = 64 * PB;
    constexpr int STGT = 2 * A_SUBT + 2 * B_SUBT;
    constexpr int NTASK = 512 * AT + 256 * BT;  // 16B copy tasks per k32 chunk
    constexpr int NIT = NTASK / 256;

    extern __shared__ uint32_t smem32[];

    if (FUSEC && blockIdx.y >= QL / BM) {
        // ---- fused c-split tile (identical math to split_c_fused_kernel) ----
        float (*tile)[33] = (float(*)[33])smem32;   // 32x33 floats in dyn smem
        const int idx = (blockIdx.y - QL / BM) * 16 + blockIdx.x;  // 0..2047
        const int b  = blockIdx.z;
        const int k0 = (idx & 63) * 32;             // CL/32 = 64 tiles
        const int d0 = (idx >> 6) * 32;             // DIM/32 = 32 tiles
        const int tx = threadIdx.x & 31;
        const int ty = threadIdx.x >> 5;

        #pragma unroll
        for (int r = 0; r < 32; r += 8) {
            float f = cfp[(long)(k0 + ty + r) * (BATCH * DIM) + (long)b * DIM + d0 + tx];
            tile[ty + r][tx] = f;
            __half h, l;
            splith(f, h, l);
            long oidx = ((long)b * CL + k0 + ty + r) * DIM + d0 + tx;  // [B,CL,DIM]
            csh[oidx] = h;
            csl[oidx] = l;
        }
        __syncthreads();
        #pragma unroll
        for (int r = 0; r < 32; r += 8) {
            long oidx = ((long)b * DIM + d0 + ty + r) * CL + k0 + tx;  // [B,DIM,CL]
            cth[oidx] = __float2half_rn(tile[tx][ty + r]);
        }
        return;
    }

    const uint32_t smem_addr = (uint32_t)__cvta_generic_to_shared(smem32);

    const int bi = blockIdx.z;
    const int m0 = blockIdx.y * BM;
    const int n0 = blockIdx.x * BN;
    const int tid  = threadIdx.x;
    const int lane = tid & 31;
    const int wid  = tid >> 5;
    const int wm = (wid & 3) * 32;     // warp m offset
    const int wn = (wid >> 2) * 32;    // warp n offset
    const int g  = lane >> 2;
    const int t  = lane & 3;

    const bool useL = (AT == 2) || (BT == 2);

    const __half* A0h_b = Ah + (long)bi * Abs;
    const __half* A0l_b = (AT == 2) ? (Al + (long)bi * Abs) : A0h_b;
    const __half* A1h_b = CONCAT ? (A1h + (long)bi * Abs) : A0h_b;
    const __half* A1l_b = (CONCAT && AT == 2) ? (A1l + (long)bi * Abs) : A1h_b;
    const __half* Bh_b  = Bh + (long)bi * Bbs;
    const __half* Bl_b  = (BT == 2) ? (Bl + (long)bi * Bbs) : Bh_b;

    // ldmatrix per-lane byte offsets (within a k16 subtile region)
    const int laA = lane & 15, sgA = lane >> 4;
    uint32_t offA[2];
    #pragma unroll
    for (int i = 0; i < 2; i++)
        offA[i] = (uint32_t)(((wm + i * 16 + laA) * PA + sgA * 4) * 4);
    const int laB = lane & 7, sgB = (lane >> 3) & 1;
    uint32_t offB[4];
    #pragma unroll
    for (int j = 0; j < 4; j++)
        offB[j] = (uint32_t)(((wn + j * 8 + laB) * PB + sgB * 4) * 4);

    float accH[2][4][4], accL[2][4][4];
    #pragma unroll
    for (int i = 0; i < 2; i++)
        #pragma unroll
        for (int j = 0; j < 4; j++)
            #pragma unroll
            for (int r = 0; r < 4; r++) { accH[i][j][r] = 0.f; accL[i][j][r] = 0.f; }

    const int niter = K / 32;

    // Task layout: [0, 512*AT): A (hi plane first 512, lo next 512)
    //              [512*AT, +256*BT): B (hi first 256, lo next 256)
    auto prefetch = [&](int it, int buf) {
        const int k0 = it * 32;
        const __half *pAh, *pAl; int ka;
        if (CONCAT && k0 >= Ksplit) { pAh = A1h_b; pAl = A1l_b; ka = k0 - Ksplit; }
        else                        { pAh = A0h_b; pAl = A0l_b; ka = k0; }
        const uint32_t sb32 = (uint32_t)buf * STGT;
        #pragma unroll
        for (int j = 0; j < NIT; ++j) {
            const int task = tid + j * 256;
            uint32_t dst32; const __half* src;
            if (task < 512 * AT) {                     // A tasks
                const int plane = (AT == 2) ? (task >> 9) : 0;
                const int idx = task & 511;            // subk(1) row(7) h16(1)
                const int subk = idx >> 8;
                const int row = (idx >> 1) & 127;
                const int h16 = idx & 1;
                dst32 = sb32 + (uint32_t)subk * A_SUBT + (uint32_t)row * PA
                        + (uint32_t)plane * 8 + (uint32_t)h16 * 4;
                src = (plane ? pAl : pAh) + (long)(m0 + row) * lda + ka + subk * 16 + h16 * 8;
            } else {                                   // B tasks
                const int bt = task - 512 * AT;
                const int plane = (BT == 2) ? (bt >> 8) : 0;
                const int idx = bt & 255;              // subk(1) row(6) h16(1)
                const int subk = idx >> 7;
                const int row = (idx >> 1) & 63;
                const int h16 = idx & 1;
                dst32 = sb32 + 2 * A_SUBT + (uint32_t)subk * B_SUBT + (uint32_t)row * PB
                        + (uint32_t)plane * 8 + (uint32_t)h16 * 4;
                src = (plane ? Bl_b : Bh_b) + (long)(n0 + row) * ldb + k0 + subk * 16 + h16 * 8;
            }
            cp16(smem_addr + dst32 * 4, src);
        }
    };

    prefetch(0, 0);
    cp_commit();
    if (niter > 1) prefetch(1, 1);
    cp_commit();

    for (int it = 0; it < niter; it++) {
        const int buf = it % NSTG;
        cp_wait1();
        __syncthreads();
        // Single barrier per chunk: orders all warps' compute of it-1 before
        // prefetch into buffer (it+2)%3 == (it-1)%3.
        if (it + 2 < niter) prefetch(it + 2, (it + 2) % NSTG);
        cp_commit();

        const uint32_t sb32 = (uint32_t)buf * STGT;
        #pragma unroll
        for (int s = 0; s < 2; ++s) {                 // two k16 substeps
            const uint32_t subA = smem_addr + (sb32 + (uint32_t)s * A_SUBT) * 4;
            const uint32_t subB = smem_addr + (sb32 + 2 * A_SUBT + (uint32_t)s * B_SUBT) * 4;

            uint32_t ah[2][4], al[2][4], bh[4][2], bl[4][2];
            ldmx4(ah[0], subA + offA[0]);
            ldmx4(ah[1], subA + offA[1]);
            if (AT == 2) {
                ldmx4(al[0], subA + offA[0] + 32);    // lo plane at +8 b32
                ldmx4(al[1], subA + offA[1] + 32);
            }
            #pragma unroll
            for (int j = 0; j < 4; j++) {
                ldmx2(bh[j], subB + offB[j]);
                if (BT == 2) ldmx2(bl[j], subB + offB[j] + 32);
            }
            // term-outer: each group of 8 MMAs mutually independent
            #pragma unroll
            for (int i = 0; i < 2; i++)
                #pragma unroll
                for (int j = 0; j < 4; j++)
                    mma16(accH[i][j], ah[i], bh[j]);
            if (AT == 2)
                #pragma unroll
                for (int i = 0; i < 2; i++)
                    #pragma unroll
                    for (int j = 0; j < 4; j++)
                        mma16(accL[i][j], al[i], bh[j]);
            if (BT == 2)
                #pragma unroll
                for (int i = 0; i < 2; i++)
                    #pragma unroll
                    for (int j = 0; j < 4; j++)
                        mma16(accL[i][j], ah[i], bl[j]);
        }
    }

    // epilogue: c0(g,2t) c1(g,2t+1) c2(g+8,2t) c3(g+8,2t+1)
    const float inv2048 = 1.0f / 2048.0f;
    #pragma unroll
    for (int i = 0; i < 2; i++) {
        const int r0 = m0 + wm + i * 16 + g;
        #pragma unroll
        for (int j = 0; j < 4; j++) {
            const int cc = n0 + wn + j * 8 + t * 2;
            float v0 = accH[i][j][0], v1 = accH[i][j][1];
            float v2 = accH[i][j][2], v3 = accH[i][j][3];
            if (useL) {
                v0 += accL[i][j][0] * inv2048;
                v1 += accL[i][j][1] * inv2048;
                v2 += accL[i][j][2] * inv2048;
                v3 += accL[i][j][3] * inv2048;
            }
            if (MODE == 0) {
                __half* Ch = (__half*)Cv  + (long)bi * Cbs;
                __half* Cl = (__half*)Cv2 + (long)bi * Cbs;
                __half h0, l0, h1, l1;
                splith(v0, h0, l0); splith(v1, h1, l1);
                *(__half2*)&Ch[(long)r0 * ldc + cc] = __halves2half2(h0, h1);
                *(__half2*)&Cl[(long)r0 * ldc + cc] = __halves2half2(l0, l1);
                splith(v2, h0, l0); splith(v3, h1, l1);
                *(__half2*)&Ch[(long)(r0 + 8) * ldc + cc] = __halves2half2(h0, h1);
                *(__half2*)&Cl[(long)(r0 + 8) * ldc + cc] = __halves2half2(l0, l1);
            } else if (MODE == 3) {
                __half* Ch = (__half*)Cv + (long)bi * Cbs;
                *(__half2*)&Ch[(long)r0 * ldc + cc] =
                    __halves2half2(__float2half_rn(v0), __float2half_rn(v1));
                *(__half2*)&Ch[(long)(r0 + 8) * ldc + cc] =
                    __halves2half2(__float2half_rn(v2), __float2half_rn(v3));
            } else {
                float* Cp = (float*)Cv + (long)bi * Cbs;
                if (MODE == 2) {
                    v0 = fast_tanh(v0); v1 = fast_tanh(v1);
                    v2 = fast_tanh(v2); v3 = fast_tanh(v3);
                }
                *(float2*)&Cp[(long)r0 * ldc + cc]       = make_float2(v0, v1);
                *(float2*)&Cp[(long)(r0 + 8) * ldc + cc] = make_float2(v2, v3);
            }
        }
    }
}

// ---------------------------------------------------------------------------
// in[r0, r1, L] fp32 -> hi/lo fp16 planes at [(r1*R0 + r0)*L]  (dim swap+split)
// ---------------------------------------------------------------------------
__global__ __launch_bounds__(256)
void split_swap_h_kernel(const float* __restrict__ in,
                         __half* __restrict__ oh, __half* __restrict__ ol,
                         int R1, int L)
{
    const long r0 = blockIdx.x, r1 = blockIdx.y;
    const float* src = in + (r0 * R1 + r1) * (long)L;
    const long dbase = (r1 * gridDim.x + r0) * (long)L;
    for (int i = threadIdx.x * 4; i < L; i += blockDim.x * 4) {
        float4 v = *(const float4*)(src + i);
        __half h0, l0, h1, l1, h2, l2, h3, l3;
        splith(v.x, h0, l0); splith(v.y, h1, l1);
        splith(v.z, h2, l2); splith(v.w, h3, l3);
        *(__half2*)&oh[dbase + i]     = __halves2half2(h0, h1);
        *(__half2*)&oh[dbase + i + 2] = __halves2half2(h2, h3);
        if (ol) {
            *(__half2*)&ol[dbase + i]     = __halves2half2(l0, l1);
            *(__half2*)&ol[dbase + i + 2] = __halves2half2(l2, l3);
        }
    }
}

// ---------------------------------------------------------------------------
// softmax over rows of 2048: fp32 probs in place + hi fp16 plane (float4 I/O)
// ---------------------------------------------------------------------------
__global__ __launch_bounds__(256)
void softmax_split_kernel(float* __restrict__ S, __half* __restrict__ sh)
{
    const long rbase = (long)blockIdx.x * 2048;
    float* row = S + rbase;
    const int t = threadIdx.x;
    __shared__ float sred[8];

    float4 v[2];
    v[0] = *(const float4*)(row + t * 4);
    v[1] = *(const float4*)(row + 1024 + t * 4);
    float mx = fmaxf(fmaxf(v[0].x, v[0].y), fmaxf(v[0].z, v[0].w));
    mx = fmaxf(mx, fmaxf(fmaxf(v[1].x, v[1].y), fmaxf(v[1].z, v[1].w)));
    #pragma unroll
    for (int o = 16; o > 0; o >>= 1)
        mx = fmaxf(mx, __shfl_xor_sync(0xffffffffu, mx, o));
    if ((t & 31) == 0) sred[t >> 5] = mx;
    __syncthreads();
    mx = sred[0];
    #pragma unroll
    for (int w = 1; w < 8; w++) mx = fmaxf(mx, sred[w]);

    float s = 0.f;
    #pragma unroll
    for (int j = 0; j < 2; j++) {
        v[j].x = __expf(v[j].x - mx); v[j].y = __expf(v[j].y - mx);
        v[j].z = __expf(v[j].z - mx); v[j].w = __expf(v[j].w - mx);
        s += (v[j].x + v[j].y) + (v[j].z + v[j].w);
    }
    #pragma unroll
    for (int o = 16; o > 0; o >>= 1)
        s += __shfl_xor_sync(0xffffffffu, s, o);
    __syncthreads();
    if ((t & 31) == 0) sred[t >> 5] = s;
    __syncthreads();
    s = 0.f;
    #pragma unroll
    for (int w = 0; w < 8; w++) s += sred[w];

    const float inv = 1.f / s;
    #pragma unroll
    for (int j = 0; j < 2; j++) {
        v[j].x *= inv; v[j].y *= inv; v[j].z *= inv; v[j].w *= inv;
        *(float4*)(row + j * 1024 + t * 4) = v[j];
        __half2 h01 = __halves2half2(__float2half_rn(v[j].x), __float2half_rn(v[j].y));
        __half2 h23 = __halves2half2(__float2half_rn(v[j].z), __float2half_rn(v[j].w));
        *(__half2*)(sh + rbase + j * 1024 + t * 4)     = h01;
        *(__half2*)(sh + rbase + j * 1024 + t * 4 + 2) = h23;
    }
}

// ---------------------------------------------------------------------------
extern "C" void kernel_launch(void* const* d_in, const int* in_sizes, int n_in,
                              void* d_out, int out_size)
{
    (void)in_sizes; (void)n_in; (void)out_size;
    const float* q     = (const float*)d_in[0];   // [QL, B, DIM]
    const float* c     = (const float*)d_in[1];   // [CL, B, DIM]
    const float* W_in  = (const float*)d_in[2];   // [DIM, DIM]
    const float* W_out = (const float*)d_in[3];   // [DIM, 2*DIM]

    float* out   = (float*)d_out;                       // [QL, B, DIM]
    float* score = out + (size_t)QL * BATCH * DIM;      // [B, QL, CL]

    __half *qsph, *qspl, *csph, *cspl, *ctsph;
    __half *wisph, *wispl, *wosph;
    __half *qbsph, *qbspl, *ssph, *ctxsph;
    cudaGetSymbolAddress((void**)&qsph,  g_qsph);  cudaGetSymbolAddress((void**)&qspl,  g_qspl);
    cudaGetSymbolAddress((void**)&csph,  g_csph);  cudaGetSymbolAddress((void**)&cspl,  g_cspl);
    cudaGetSymbolAddress((void**)&ctsph, g_ctsph);
    cudaGetSymbolAddress((void**)&wisph, g_wisph); cudaGetSymbolAddress((void**)&wispl, g_wispl);
    cudaGetSymbolAddress((void**)&wosph, g_wosph);
    cudaGetSymbolAddress((void**)&qbsph, g_qbsph); cudaGetSymbolAddress((void**)&qbspl, g_qbspl);
    cudaGetSymbolAddress((void**)&ssph,  g_ssph);
    cudaGetSymbolAddress((void**)&ctxsph, g_ctxsph);

    cudaFuncSetAttribute(gemm_h3_kernel<2, 2, 0, false, true >, cudaFuncAttributeMaxDynamicSharedMemorySize, SMEM_22);
    cudaFuncSetAttribute(gemm_h3_kernel<2, 2, 1, false, false>, cudaFuncAttributeMaxDynamicSharedMemorySize, SMEM_22);
    cudaFuncSetAttribute(gemm_h3_kernel<1, 1, 3, false, false>, cudaFuncAttributeMaxDynamicSharedMemorySize, SMEM_11);
    cudaFuncSetAttribute(gemm_h3_kernel<1, 1, 2, true,  false>, cudaFuncAttributeMaxDynamicSharedMemorySize, SMEM_11);

    const long sQB = (long)QL * DIM;       // per-batch strides
    const long sSC = (long)QL * CL;

    // -- pre-split passes (q + weights only; c-split rides inside stage 1) --
    split_swap_h_kernel<<<dim3(QL, BATCH), 256>>>(q, qsph, qspl, BATCH, DIM);
    split_swap_h_kernel<<<dim3(DIM, 1), 256>>>(W_in,  wisph, wispl, 1, DIM);
    split_swap_h_kernel<<<dim3(DIM, 1), 256>>>(W_out, wosph, nullptr, 1, 2 * DIM);

    // -- stage 1: qb = q . W_in^T  (2x2 planes, split fp16 out)
    //    + fused c-split tiles on blockIdx.y >= 8 (co-resident DRAM work) --
    gemm_h3_kernel<2, 2, 0, false, true><<<dim3(DIM / BN, QL / BM + FUSE_YT, BATCH), 256, SMEM_22>>>(
        qsph, qspl, nullptr, nullptr, sQB, DIM,
        wisph, wispl, 0, DIM,
        qbsph, qbspl, sQB, DIM,
        DIM, 0,
        c, csph, cspl, ctsph);

    // -- stage 2: score = qb . c^T  (2x2 planes, fp32 into output region) --
    gemm_h3_kernel<2, 2, 1, false, false><<<dim3(CL / BN, QL / BM, BATCH), 256, SMEM_22>>>(
        qbsph, qbspl, nullptr, nullptr, sQB, DIM,
        csph, cspl, (long)CL * DIM, DIM,
        score, nullptr, sSC, CL,
        DIM, 0,
        nullptr, nullptr, nullptr, nullptr);

    // -- stage 3: softmax (fp32 in place + hi plane) --
    softmax_split_kernel<<<BATCH * QL, 256>>>(score, ssph);

    // -- stage 4: ctx = P . c  (1x1 planes, compact smem, occ 3) --
    gemm_h3_kernel<1, 1, 3, false, false><<<dim3(DIM / BN, QL / BM, BATCH), 256, SMEM_11>>>(
        ssph, nullptr, nullptr, nullptr, sSC, CL,
        ctsph, nullptr, (long)DIM * CL, CL,
        ctxsph, nullptr, sQB, DIM,
        CL, 0,
        nullptr, nullptr, nullptr, nullptr);

    // -- stage 5: out = tanh([ctx|qb] . W_out^T)  (1x1 planes, occ 3) --
    gemm_h3_kernel<1, 1, 2, true, false><<<dim3(DIM / BN, QL / BM, BATCH), 256, SMEM_11>>>(
        ctxsph, nullptr, qbsph, nullptr, sQB, DIM,
        wosph, nullptr, 0, 2 * DIM,
        out, nullptr, DIM, (long)BATCH * DIM,
        2 * DIM, DIM,
        nullptr, nullptr, nullptr, nullptr);
}